// round 5
// baseline (speedup 1.0000x reference)
#include <cuda_runtime.h>

#define FM 0xffffffffu

__device__ __forceinline__ float artanh_(float x) {
    x = fminf(fmaxf(x, -1.f + 1e-7f), 1.f - 1e-7f);
    return 0.5f * logf((1.f + x) / (1.f - x));
}

__device__ __forceinline__ float wred32(float v) {
#pragma unroll
    for (int o = 16; o; o >>= 1) v += __shfl_xor_sync(FM, v, o);
    return v;
}

__device__ __forceinline__ float gred16(float v) {
#pragma unroll
    for (int o = 8; o; o >>= 1) v += __shfl_xor_sync(FM, v, o);
    return v;
}

enum { X2SELF = 0, X2IV, FSELF, FIV,
       N2AGGE, N2AGGU, DSAE, DIAU,
       N2KG, DSKG, N2UA, N2O1, DO1UA,
       XN2, MXN2, NB2, NRES2, NHB2, DRH, N2O3, N2T, NSC };

__global__ __launch_bounds__(256)
void kgagg_kernel(const float* __restrict__ g_self,   // (B,1,64)
                  const float* __restrict__ g_ungh,   // (B,16,64)
                  const float* __restrict__ g_engh,   // (B,1,16,64)
                  const float* __restrict__ g_item,   // (B,64)
                  const float* __restrict__ g_Wr,     // (B,1,16,64,64)
                  const float* __restrict__ g_Wui,    // (64,64)
                  const float* __restrict__ g_linW,   // (64,64)
                  const float* __restrict__ g_linb,   // (64,)
                  float* __restrict__ g_out)          // (B,1,64)
{
    const int b    = blockIdx.x;
    const int tid  = threadIdx.x;
    const int lane = tid & 31;
    const int warp = tid >> 5;
    const float MAXN = 1.f - 0.004f;

    __shared__ float s_self[64], s_iv[64], s_tself[64], s_titem[64];
    __shared__ float s_engh[16][64], s_ungh[16][64];
    __shared__ float s_te[16][64], s_tu[16][64];   // tengh/tungh, later reused for sub
    __shared__ float s_y2e[16], s_xye[16], s_y2u[16], s_xyu[16];
    __shared__ float s_fe[16], s_fu[16];
    __shared__ float s_e[16], s_ue[16], s_att[16], s_uatt[16];
    __shared__ float s_sn2e[16], s_sn2u[16], s_ce[16], s_cu[16];
    __shared__ float s_imW[64], s_mx[64];
    __shared__ float s_aggE[64], s_aggU[64], s_kg[64], s_ua[64];
    __shared__ float s_o1[64], s_o2[64], s_res[64], s_hb[64], s_o3[64], s_t[64];
    __shared__ float sc[NSC];

    // ---------------- Phase 0: load small tensors ----------------
    if (tid < 64)            s_self[tid]      = g_self[b * 64 + tid];
    else if (tid < 128)      s_iv[tid - 64]   = g_item[b * 64 + (tid - 64)];
#pragma unroll
    for (int i = tid; i < 1024; i += 256) {
        (&s_engh[0][0])[i] = g_engh[(size_t)b * 1024 + i];
        (&s_ungh[0][0])[i] = g_ungh[(size_t)b * 1024 + i];
    }
    __syncthreads();

    // ---------------- Phase A: per-s norms/dots + self/iv norms ----------------
    {
        int g = tid >> 4, l = tid & 15;
        float pe = 0.f, pxe = 0.f, pu = 0.f, pxu = 0.f;
#pragma unroll
        for (int k = 0; k < 4; k++) {
            int d = l + 16 * k;
            float ev = s_engh[g][d]; pe += ev * ev; pxe += ev * s_self[d];
            float uv = s_ungh[g][d]; pu += uv * uv; pxu += uv * s_iv[d];
        }
        pe = gred16(pe); pxe = gred16(pxe); pu = gred16(pu); pxu = gred16(pxu);
        if (l == 0) { s_y2e[g] = pe; s_xye[g] = pxe; s_y2u[g] = pu; s_xyu[g] = pxu; }

        float v = 0.f;
        if (warp == 0)      { float a = s_self[lane], c = s_self[lane + 32]; v = a * a + c * c; }
        else if (warp == 1) { float a = s_iv[lane],   c = s_iv[lane + 32];   v = a * a + c * c; }
        v = wred32(v);
        if (lane == 0) { if (warp == 0) sc[X2SELF] = v; else if (warp == 1) sc[X2IV] = v; }
    }
    __syncthreads();

    // ---------------- Phase A2: logmap0 scale factors ----------------
    if (tid < 16) {
        float ne = fmaxf(sqrtf(s_y2e[tid]), 1e-15f);
        s_fe[tid] = artanh_(ne) / ne;
    } else if (tid < 32) {
        int s = tid - 16;
        float nu = fmaxf(sqrtf(s_y2u[s]), 1e-15f);
        s_fu[s] = artanh_(nu) / nu;
    } else if (tid == 32) {
        float n = fmaxf(sqrtf(sc[X2SELF]), 1e-15f);
        sc[FSELF] = artanh_(n) / n;
    } else if (tid == 33) {
        float n = fmaxf(sqrtf(sc[X2IV]), 1e-15f);
        sc[FIV] = artanh_(n) / n;
    }
    __syncthreads();

    // ---------------- Phase B: apply logmap0 ----------------
    if (tid < 64)       s_tself[tid]      = sc[FSELF] * s_self[tid];
    else if (tid < 128) s_titem[tid - 64] = sc[FIV]   * s_iv[tid - 64];
#pragma unroll
    for (int i = tid; i < 1024; i += 256) {
        int s = i >> 6;
        (&s_te[0][0])[i] = s_fe[s] * (&s_engh[0][0])[i];
        (&s_tu[0][0])[i] = s_fu[s] * (&s_ungh[0][0])[i];
    }
    __syncthreads();

    // ---------------- Phase C: e[s] = sum_{r,c} tengh[s,r]*tself[c]*Wr[s,r,c] ----------------
    // Warp-coalesced float2 stream of the 256KB Wr slab for this batch element.
    {
        const float2* W2 = reinterpret_cast<const float2*>(g_Wr) + (size_t)b * 32768;
        float a0 = s_tself[2 * lane], a1 = s_tself[2 * lane + 1];
#pragma unroll
        for (int si = warp; si < 16; si += 8) {
            const float2* p = W2 + si * 2048 + lane;
            float acc = 0.f;
#pragma unroll 8
            for (int r = 0; r < 64; r++) {
                float2 w = p[r * 32];
                acc += s_te[si][r] * (w.x * a0 + w.y * a1);
            }
            acc = wred32(acc);
            if (lane == 0) s_e[si] = acc;
        }
        // imW[r] = sum_d t_item[d] * W_ui[r,d]
#pragma unroll
        for (int r = warp; r < 64; r += 8) {
            float v = g_Wui[r * 64 + lane] * s_titem[lane]
                    + g_Wui[r * 64 + lane + 32] * s_titem[lane + 32];
            v = wred32(v);
            if (lane == 0) s_imW[r] = v;
        }
    }
    __syncthreads();

    // ---------------- Phase D: u_e[s] = dot(imW, t_ungh[s]) ----------------
    {
        int g = tid >> 4, l = tid & 15;
        float p = 0.f;
#pragma unroll
        for (int k = 0; k < 4; k++) { int r = l + 16 * k; p += s_imW[r] * s_tu[g][r]; }
        p = gred16(p);
        if (l == 0) s_ue[g] = p;
    }
    __syncthreads();

    // ---------------- Phase E: softmaxes over s (16 values each) ----------------
    if (warp < 2) {
        const float* src = (warp == 0) ? s_e : s_ue;
        float* dst       = (warp == 0) ? s_att : s_uatt;
        float v = (lane < 16) ? src[lane] : -1e30f;
        float m = v;
#pragma unroll
        for (int o = 16; o; o >>= 1) m = fmaxf(m, __shfl_xor_sync(FM, m, o));
        float ex = (lane < 16) ? expf(v - m) : 0.f;
        float sum = wred32(ex);
        if (lane < 16) dst[lane] = ex / sum;
    }
    __syncthreads();

    // ---------------- Phase F: sub = mobius_add(-p, y) for entity & user ----------------
    {
        float x2s = sc[X2SELF], x2i = sc[X2IV];
#pragma unroll
        for (int i = tid; i < 2048; i += 256) {
            if (i < 1024) {
                int s = i >> 6, d = i & 63;
                float t2 = 2.f * s_xye[s];
                float cx = -(1.f - t2 + s_y2e[s]);
                float cy = 1.f - x2s;
                float den = fmaxf(1.f - t2 + x2s * s_y2e[s], 1e-15f);
                (&s_te[0][0])[i] = (cx * s_self[d] + cy * s_engh[s][d]) / den;
            } else {
                int j = i - 1024, s = j >> 6, d = j & 63;
                float t2 = 2.f * s_xyu[s];
                float cx = -(1.f - t2 + s_y2u[s]);
                float cy = 1.f - x2i;
                float den = fmaxf(1.f - t2 + x2i * s_y2u[s], 1e-15f);
                (&s_tu[0][0])[j] = (cx * s_iv[d] + cy * s_ungh[s][d]) / den;
            }
        }
    }
    __syncthreads();

    // sub norms
    {
        int g = tid >> 4, l = tid & 15;
        float pe = 0.f, pu = 0.f;
#pragma unroll
        for (int k = 0; k < 4; k++) {
            int d = l + 16 * k;
            float v = s_te[g][d]; pe += v * v;
            float u = s_tu[g][d]; pu += u * u;
        }
        pe = gred16(pe); pu = gred16(pu);
        if (l == 0) { s_sn2e[g] = pe; s_sn2u[g] = pu; }
    }
    __syncthreads();

    // att-weighted logmap coefficients
    if (tid < 16) {
        float lam = fmaxf(2.f / (1.f - sc[X2SELF]), 1e-15f);
        float sn  = fmaxf(sqrtf(s_sn2e[tid]), 1e-15f);
        s_ce[tid] = s_att[tid] * (2.f / lam) * artanh_(sn) / sn;
    } else if (tid < 32) {
        int s = tid - 16;
        float lam = fmaxf(2.f / (1.f - sc[X2IV]), 1e-15f);
        float sn  = fmaxf(sqrtf(s_sn2u[s]), 1e-15f);
        s_cu[s] = s_uatt[s] * (2.f / lam) * artanh_(sn) / sn;
    }
    __syncthreads();

    // aggregate over s
    if (tid < 64) {
        float a = 0.f;
#pragma unroll
        for (int s = 0; s < 16; s++) a += s_ce[s] * s_te[s][tid];
        s_aggE[tid] = a;
    } else if (tid < 128) {
        int d = tid - 64;
        float a = 0.f;
#pragma unroll
        for (int s = 0; s < 16; s++) a += s_cu[s] * s_tu[s][d];
        s_aggU[d] = a;
    }
    __syncthreads();

    // R1: norms/dots of aggregates
    {
        float v = 0.f;
        if (warp == 0)      v = s_aggE[lane] * s_aggE[lane] + s_aggE[lane + 32] * s_aggE[lane + 32];
        else if (warp == 1) v = s_aggU[lane] * s_aggU[lane] + s_aggU[lane + 32] * s_aggU[lane + 32];
        else if (warp == 2) v = s_self[lane] * s_aggE[lane] + s_self[lane + 32] * s_aggE[lane + 32];
        else if (warp == 3) v = s_iv[lane]   * s_aggU[lane] + s_iv[lane + 32]   * s_aggU[lane + 32];
        v = wred32(v);
        if (lane == 0) {
            if (warp == 0) sc[N2AGGE] = v; else if (warp == 1) sc[N2AGGU] = v;
            else if (warp == 2) sc[DSAE] = v; else if (warp == 3) sc[DIAU] = v;
        }
    }
    __syncthreads();

    // expmap at base point + mobius_add(base, second)  -> kg, ua
    {
        float x2s = sc[X2SELF], x2i = sc[X2IV];
        if (tid < 64) {
            float un  = fmaxf(sqrtf(sc[N2AGGE]), 1e-15f);
            float lam = fmaxf(2.f / (1.f - x2s), 1e-15f);
            float f   = tanhf(lam * un * 0.5f) / un;
            float xy = f * sc[DSAE], y2 = f * f * sc[N2AGGE];
            float den = fmaxf(1.f + 2.f * xy + x2s * y2, 1e-15f);
            s_kg[tid] = ((1.f + 2.f * xy + y2) * s_self[tid] + (1.f - x2s) * f * s_aggE[tid]) / den;
        } else if (tid < 128) {
            int d = tid - 64;
            float un  = fmaxf(sqrtf(sc[N2AGGU]), 1e-15f);
            float lam = fmaxf(2.f / (1.f - x2i), 1e-15f);
            float f   = tanhf(lam * un * 0.5f) / un;
            float xy = f * sc[DIAU], y2 = f * f * sc[N2AGGU];
            float den = fmaxf(1.f + 2.f * xy + x2i * y2, 1e-15f);
            s_ua[d] = ((1.f + 2.f * xy + y2) * s_iv[d] + (1.f - x2i) * f * s_aggU[d]) / den;
        }
    }
    __syncthreads();

    // R2
    {
        float v = 0.f;
        if (warp == 0)      v = s_kg[lane] * s_kg[lane]   + s_kg[lane + 32] * s_kg[lane + 32];
        else if (warp == 1) v = s_self[lane] * s_kg[lane] + s_self[lane + 32] * s_kg[lane + 32];
        else if (warp == 2) v = s_ua[lane] * s_ua[lane]   + s_ua[lane + 32] * s_ua[lane + 32];
        v = wred32(v);
        if (lane == 0) {
            if (warp == 0) sc[N2KG] = v; else if (warp == 1) sc[DSKG] = v;
            else if (warp == 2) sc[N2UA] = v;
        }
    }
    __syncthreads();

    // o1 = mobius_add(self, kg)
    if (tid < 64) {
        float x2 = sc[X2SELF], y2 = sc[N2KG], xy = sc[DSKG];
        float den = fmaxf(1.f + 2.f * xy + x2 * y2, 1e-15f);
        s_o1[tid] = ((1.f + 2.f * xy + y2) * s_self[tid] + (1.f - x2) * s_kg[tid]) / den;
    }
    __syncthreads();

    // R3
    {
        float v = 0.f;
        if (warp == 0)      v = s_o1[lane] * s_o1[lane] + s_o1[lane + 32] * s_o1[lane + 32];
        else if (warp == 1) v = s_o1[lane] * s_ua[lane] + s_o1[lane + 32] * s_ua[lane + 32];
        v = wred32(v);
        if (lane == 0) { if (warp == 0) sc[N2O1] = v; else if (warp == 1) sc[DO1UA] = v; }
    }
    __syncthreads();

    // o2 = mobius_add(o1, ua)
    if (tid < 64) {
        float x2 = sc[N2O1], y2 = sc[N2UA], xy = sc[DO1UA];
        float den = fmaxf(1.f + 2.f * xy + x2 * y2, 1e-15f);
        s_o2[tid] = ((1.f + 2.f * xy + y2) * s_o1[tid] + (1.f - x2) * s_ua[tid]) / den;
    }
    __syncthreads();

    // mx = lin_W @ o2
#pragma unroll
    for (int r = warp; r < 64; r += 8) {
        float v = g_linW[r * 64 + lane] * s_o2[lane]
                + g_linW[r * 64 + lane + 32] * s_o2[lane + 32];
        v = wred32(v);
        if (lane == 0) s_mx[r] = v;
    }
    __syncthreads();

    // R5
    {
        float v = 0.f;
        if (warp == 0)      { float a = s_mx[lane],    c = s_mx[lane + 32];    v = a * a + c * c; }
        else if (warp == 1) { float a = g_linb[lane],  c = g_linb[lane + 32];  v = a * a + c * c; }
        else if (warp == 2) { float a = s_o2[lane],    c = s_o2[lane + 32];    v = a * a + c * c; }
        v = wred32(v);
        if (lane == 0) {
            if (warp == 0) sc[MXN2] = v; else if (warp == 1) sc[NB2] = v;
            else if (warp == 2) sc[XN2] = v;
        }
    }
    __syncthreads();

    // res = mobius_matvec scale; hb = expmap0(lin_b)
    if (tid < 64) {
        float xn  = fmaxf(sqrtf(sc[XN2]),  1e-15f);
        float mxn = fmaxf(sqrtf(sc[MXN2]), 1e-15f);
        float f = tanhf(mxn / xn * artanh_(xn)) / mxn;
        s_res[tid] = f * s_mx[tid];
    } else if (tid < 128) {
        int d = tid - 64;
        float nb = fmaxf(sqrtf(sc[NB2]), 1e-15f);
        float f = tanhf(nb) / nb;
        s_hb[d] = f * g_linb[d];
    }
    __syncthreads();

    // R6
    {
        float v = 0.f;
        if (warp == 0)      v = s_res[lane] * s_res[lane] + s_res[lane + 32] * s_res[lane + 32];
        else if (warp == 1) v = s_hb[lane]  * s_hb[lane]  + s_hb[lane + 32]  * s_hb[lane + 32];
        else if (warp == 2) v = s_res[lane] * s_hb[lane]  + s_res[lane + 32] * s_hb[lane + 32];
        v = wred32(v);
        if (lane == 0) {
            if (warp == 0) sc[NRES2] = v; else if (warp == 1) sc[NHB2] = v;
            else if (warp == 2) sc[DRH] = v;
        }
    }
    __syncthreads();

    // o3 = mobius_add(proj(res), proj(hb))
    if (tid < 64) {
        float nr = fmaxf(sqrtf(sc[NRES2]), 1e-15f);
        float pr = (nr > MAXN) ? MAXN / nr : 1.f;
        float nh = fmaxf(sqrtf(sc[NHB2]), 1e-15f);
        float ph = (nh > MAXN) ? MAXN / nh : 1.f;
        float x2 = pr * pr * sc[NRES2];
        float y2 = ph * ph * sc[NHB2];
        float xy = pr * ph * sc[DRH];
        float den = fmaxf(1.f + 2.f * xy + x2 * y2, 1e-15f);
        s_o3[tid] = ((1.f + 2.f * xy + y2) * pr * s_res[tid] + (1.f - x2) * ph * s_hb[tid]) / den;
    }
    __syncthreads();

    // R7
    {
        float v = 0.f;
        if (warp == 0) v = s_o3[lane] * s_o3[lane] + s_o3[lane + 32] * s_o3[lane + 32];
        v = wred32(v);
        if (lane == 0 && warp == 0) sc[N2O3] = v;
    }
    __syncthreads();

    // t = tanh(logmap0(proj(o3)))
    if (tid < 64) {
        float n3 = fmaxf(sqrtf(sc[N2O3]), 1e-15f);
        float p3 = (n3 > MAXN) ? MAXN / n3 : 1.f;
        float np = fmaxf(p3 * n3, 1e-15f);
        float fL = artanh_(np) / np;
        s_t[tid] = tanhf(fL * p3 * s_o3[tid]);
    }
    __syncthreads();

    // R8
    {
        float v = 0.f;
        if (warp == 0) v = s_t[lane] * s_t[lane] + s_t[lane + 32] * s_t[lane + 32];
        v = wred32(v);
        if (lane == 0 && warp == 0) sc[N2T] = v;
    }
    __syncthreads();

    // out = expmap0(t)
    if (tid < 64) {
        float nt = fmaxf(sqrtf(sc[N2T]), 1e-15f);
        float f = tanhf(nt) / nt;
        g_out[b * 64 + tid] = f * s_t[tid];
    }
}

extern "C" void kernel_launch(void* const* d_in, const int* in_sizes, int n_in,
                              void* d_out, int out_size) {
    // inputs (metadata order): self_vectors, ngh_user_vectors, ngh_entity_vectors,
    //                          item_embeddings, Wr, W_ui, lin_W, lin_b
    int B = in_sizes[0] / 64;
    kgagg_kernel<<<B, 256>>>(
        (const float*)d_in[0],  // self_vectors
        (const float*)d_in[1],  // ngh_user_vectors
        (const float*)d_in[2],  // ngh_entity_vectors
        (const float*)d_in[3],  // item_embeddings
        (const float*)d_in[4],  // Wr
        (const float*)d_in[5],  // W_ui
        (const float*)d_in[6],  // lin_W
        (const float*)d_in[7],  // lin_b
        (float*)d_out);
}

// round 8
// speedup vs baseline: 1.0161x; 1.0161x over previous
#include <cuda_runtime.h>

#define FM 0xffffffffu

__device__ __forceinline__ float artanh_(float x) {
    x = fminf(fmaxf(x, -1.f + 1e-7f), 1.f - 1e-7f);
    return 0.5f * logf((1.f + x) / (1.f - x));
}

__device__ __forceinline__ float wred32(float v) {
#pragma unroll
    for (int o = 16; o; o >>= 1) v += __shfl_xor_sync(FM, v, o);
    return v;
}

__device__ __forceinline__ float gred16(float v) {
#pragma unroll
    for (int o = 8; o; o >>= 1) v += __shfl_xor_sync(FM, v, o);
    return v;
}

enum { X2SELF = 0, X2IV, FSELF, FIV,
       N2AGGE, N2AGGU, DSAE, DIAU,
       N2KG, DSKG, N2UA, N2O1, DO1UA,
       XN2, MXN2, NB2, NRES2, NHB2, DRH, N2O3, N2T, NSC };

__global__ __launch_bounds__(256)
void kgagg_kernel(const float* __restrict__ g_self,   // (B,1,64)
                  const float* __restrict__ g_ungh,   // (B,16,64)
                  const float* __restrict__ g_engh,   // (B,1,16,64)
                  const float* __restrict__ g_item,   // (B,64)
                  const float* __restrict__ g_Wr,     // (B,1,16,64,64)
                  const float* __restrict__ g_Wui,    // (64,64)
                  const float* __restrict__ g_linW,   // (64,64)
                  const float* __restrict__ g_linb,   // (64,)
                  float* __restrict__ g_out)          // (B,1,64)
{
    const int b    = blockIdx.x;
    const int tid  = threadIdx.x;
    const int lane = tid & 31;
    const int warp = tid >> 5;
    const float MAXN = 1.f - 0.004f;

    __shared__ float s_self[64], s_iv[64], s_tself[64], s_titem[64];
    __shared__ float s_engh[16][64], s_ungh[16][64];
    __shared__ float s_te[16][64], s_tu[16][64];   // tengh/tungh, later reused for sub
    __shared__ float s_y2e[16], s_xye[16], s_y2u[16], s_xyu[16];
    __shared__ float s_fe[16], s_fu[16];
    __shared__ float s_e[16], s_ue[16], s_att[16], s_uatt[16];
    __shared__ float s_sn2e[16], s_sn2u[16], s_ce[16], s_cu[16];
    __shared__ float s_imW[64], s_mx[64];
    __shared__ float s_aggE[64], s_aggU[64], s_kg[64], s_ua[64];
    __shared__ float s_o1[64], s_o2[64], s_res[64], s_hb[64], s_o3[64], s_t[64];
    __shared__ float sc[NSC];

    // ---------------- Phase 0: load small tensors ----------------
    if (tid < 64)            s_self[tid]      = g_self[b * 64 + tid];
    else if (tid < 128)      s_iv[tid - 64]   = g_item[b * 64 + (tid - 64)];
#pragma unroll
    for (int i = tid; i < 1024; i += 256) {
        (&s_engh[0][0])[i] = g_engh[(size_t)b * 1024 + i];
        (&s_ungh[0][0])[i] = g_ungh[(size_t)b * 1024 + i];
    }
    __syncthreads();

    // ---------------- Phase A: per-s norms/dots + self/iv norms ----------------
    {
        int g = tid >> 4, l = tid & 15;
        float pe = 0.f, pxe = 0.f, pu = 0.f, pxu = 0.f;
#pragma unroll
        for (int k = 0; k < 4; k++) {
            int d = l + 16 * k;
            float ev = s_engh[g][d]; pe += ev * ev; pxe += ev * s_self[d];
            float uv = s_ungh[g][d]; pu += uv * uv; pxu += uv * s_iv[d];
        }
        pe = gred16(pe); pxe = gred16(pxe); pu = gred16(pu); pxu = gred16(pxu);
        if (l == 0) { s_y2e[g] = pe; s_xye[g] = pxe; s_y2u[g] = pu; s_xyu[g] = pxu; }

        float v = 0.f;
        if (warp == 0)      { float a = s_self[lane], c = s_self[lane + 32]; v = a * a + c * c; }
        else if (warp == 1) { float a = s_iv[lane],   c = s_iv[lane + 32];   v = a * a + c * c; }
        v = wred32(v);
        if (lane == 0) { if (warp == 0) sc[X2SELF] = v; else if (warp == 1) sc[X2IV] = v; }
    }
    __syncthreads();

    // ---------------- Phase A2: logmap0 scale factors ----------------
    if (tid < 16) {
        float ne = fmaxf(sqrtf(s_y2e[tid]), 1e-15f);
        s_fe[tid] = artanh_(ne) / ne;
    } else if (tid < 32) {
        int s = tid - 16;
        float nu = fmaxf(sqrtf(s_y2u[s]), 1e-15f);
        s_fu[s] = artanh_(nu) / nu;
    } else if (tid == 32) {
        float n = fmaxf(sqrtf(sc[X2SELF]), 1e-15f);
        sc[FSELF] = artanh_(n) / n;
    } else if (tid == 33) {
        float n = fmaxf(sqrtf(sc[X2IV]), 1e-15f);
        sc[FIV] = artanh_(n) / n;
    }
    __syncthreads();

    // ---------------- Phase B: apply logmap0 ----------------
    if (tid < 64)       s_tself[tid]      = sc[FSELF] * s_self[tid];
    else if (tid < 128) s_titem[tid - 64] = sc[FIV]   * s_iv[tid - 64];
#pragma unroll
    for (int i = tid; i < 1024; i += 256) {
        int s = i >> 6;
        (&s_te[0][0])[i] = s_fe[s] * (&s_engh[0][0])[i];
        (&s_tu[0][0])[i] = s_fu[s] * (&s_ungh[0][0])[i];
    }
    __syncthreads();

    // ---------------- Phase C: e[s] = sum_{r,c} tengh[s,r]*tself[c]*Wr[s,r,c] ----------------
    // float4 warp-coalesced stream of the 256KB Wr slab: each warp-iteration
    // covers 2 full rows (512B). Lanes 0-15 -> even row, lanes 16-31 -> odd row,
    // lane covers columns 4*(lane&15) .. +3.
    {
        const float4* W4 = reinterpret_cast<const float4*>(g_Wr) + (size_t)b * 16384;
        const int l15 = lane & 15;
        const int hi  = lane >> 4;
        const float4 a = *reinterpret_cast<const float4*>(&s_tself[4 * l15]);
#pragma unroll
        for (int sv = 0; sv < 2; sv++) {
            const int si = warp + 8 * sv;
            const float4* p = W4 + si * 1024 + lane;
            float acc = 0.f;
#pragma unroll 8
            for (int i = 0; i < 32; i++) {
                float4 w = __ldcs(p + i * 32);
                float t = s_te[si][2 * i + hi];
                acc += t * (w.x * a.x + w.y * a.y + w.z * a.z + w.w * a.w);
            }
            acc = wred32(acc);
            if (lane == 0) s_e[si] = acc;
        }
        // imW[r] = sum_d t_item[d] * W_ui[r,d]
#pragma unroll
        for (int r = warp; r < 64; r += 8) {
            float v = g_Wui[r * 64 + lane] * s_titem[lane]
                    + g_Wui[r * 64 + lane + 32] * s_titem[lane + 32];
            v = wred32(v);
            if (lane == 0) s_imW[r] = v;
        }
    }
    __syncthreads();

    // ---------------- Phase D: u_e[s] = dot(imW, t_ungh[s]) ----------------
    {
        int g = tid >> 4, l = tid & 15;
        float p = 0.f;
#pragma unroll
        for (int k = 0; k < 4; k++) { int r = l + 16 * k; p += s_imW[r] * s_tu[g][r]; }
        p = gred16(p);
        if (l == 0) s_ue[g] = p;
    }
    __syncthreads();

    // ---------------- Phase E: softmaxes over s (16 values each) ----------------
    if (warp < 2) {
        const float* src = (warp == 0) ? s_e : s_ue;
        float* dst       = (warp == 0) ? s_att : s_uatt;
        float v = (lane < 16) ? src[lane] : -1e30f;
        float m = v;
#pragma unroll
        for (int o = 16; o; o >>= 1) m = fmaxf(m, __shfl_xor_sync(FM, m, o));
        float ex = (lane < 16) ? expf(v - m) : 0.f;
        float sum = wred32(ex);
        if (lane < 16) dst[lane] = ex / sum;
    }
    __syncthreads();

    // ---------------- Phase F: sub = mobius_add(-p, y) for entity & user ----------------
    {
        float x2s = sc[X2SELF], x2i = sc[X2IV];
#pragma unroll
        for (int i = tid; i < 2048; i += 256) {
            if (i < 1024) {
                int s = i >> 6, d = i & 63;
                float t2 = 2.f * s_xye[s];
                float cx = -(1.f - t2 + s_y2e[s]);
                float cy = 1.f - x2s;
                float den = fmaxf(1.f - t2 + x2s * s_y2e[s], 1e-15f);
                (&s_te[0][0])[i] = (cx * s_self[d] + cy * s_engh[s][d]) / den;
            } else {
                int j = i - 1024, s = j >> 6, d = j & 63;
                float t2 = 2.f * s_xyu[s];
                float cx = -(1.f - t2 + s_y2u[s]);
                float cy = 1.f - x2i;
                float den = fmaxf(1.f - t2 + x2i * s_y2u[s], 1e-15f);
                (&s_tu[0][0])[j] = (cx * s_iv[d] + cy * s_ungh[s][d]) / den;
            }
        }
    }
    __syncthreads();

    // sub norms
    {
        int g = tid >> 4, l = tid & 15;
        float pe = 0.f, pu = 0.f;
#pragma unroll
        for (int k = 0; k < 4; k++) {
            int d = l + 16 * k;
            float v = s_te[g][d]; pe += v * v;
            float u = s_tu[g][d]; pu += u * u;
        }
        pe = gred16(pe); pu = gred16(pu);
        if (l == 0) { s_sn2e[g] = pe; s_sn2u[g] = pu; }
    }
    __syncthreads();

    // att-weighted logmap coefficients
    if (tid < 16) {
        float lam = fmaxf(2.f / (1.f - sc[X2SELF]), 1e-15f);
        float sn  = fmaxf(sqrtf(s_sn2e[tid]), 1e-15f);
        s_ce[tid] = s_att[tid] * (2.f / lam) * artanh_(sn) / sn;
    } else if (tid < 32) {
        int s = tid - 16;
        float lam = fmaxf(2.f / (1.f - sc[X2IV]), 1e-15f);
        float sn  = fmaxf(sqrtf(s_sn2u[s]), 1e-15f);
        s_cu[s] = s_uatt[s] * (2.f / lam) * artanh_(sn) / sn;
    }
    __syncthreads();

    // aggregate over s
    if (tid < 64) {
        float a = 0.f;
#pragma unroll
        for (int s = 0; s < 16; s++) a += s_ce[s] * s_te[s][tid];
        s_aggE[tid] = a;
    } else if (tid < 128) {
        int d = tid - 64;
        float a = 0.f;
#pragma unroll
        for (int s = 0; s < 16; s++) a += s_cu[s] * s_tu[s][d];
        s_aggU[d] = a;
    }
    __syncthreads();

    // R1: norms/dots of aggregates
    {
        float v = 0.f;
        if (warp == 0)      v = s_aggE[lane] * s_aggE[lane] + s_aggE[lane + 32] * s_aggE[lane + 32];
        else if (warp == 1) v = s_aggU[lane] * s_aggU[lane] + s_aggU[lane + 32] * s_aggU[lane + 32];
        else if (warp == 2) v = s_self[lane] * s_aggE[lane] + s_self[lane + 32] * s_aggE[lane + 32];
        else if (warp == 3) v = s_iv[lane]   * s_aggU[lane] + s_iv[lane + 32]   * s_aggU[lane + 32];
        v = wred32(v);
        if (lane == 0) {
            if (warp == 0) sc[N2AGGE] = v; else if (warp == 1) sc[N2AGGU] = v;
            else if (warp == 2) sc[DSAE] = v; else if (warp == 3) sc[DIAU] = v;
        }
    }
    __syncthreads();

    // expmap at base point + mobius_add(base, second)  -> kg, ua
    {
        float x2s = sc[X2SELF], x2i = sc[X2IV];
        if (tid < 64) {
            float un  = fmaxf(sqrtf(sc[N2AGGE]), 1e-15f);
            float lam = fmaxf(2.f / (1.f - x2s), 1e-15f);
            float f   = tanhf(lam * un * 0.5f) / un;
            float xy = f * sc[DSAE], y2 = f * f * sc[N2AGGE];
            float den = fmaxf(1.f + 2.f * xy + x2s * y2, 1e-15f);
            s_kg[tid] = ((1.f + 2.f * xy + y2) * s_self[tid] + (1.f - x2s) * f * s_aggE[tid]) / den;
        } else if (tid < 128) {
            int d = tid - 64;
            float un  = fmaxf(sqrtf(sc[N2AGGU]), 1e-15f);
            float lam = fmaxf(2.f / (1.f - x2i), 1e-15f);
            float f   = tanhf(lam * un * 0.5f) / un;
            float xy = f * sc[DIAU], y2 = f * f * sc[N2AGGU];
            float den = fmaxf(1.f + 2.f * xy + x2i * y2, 1e-15f);
            s_ua[d] = ((1.f + 2.f * xy + y2) * s_iv[d] + (1.f - x2i) * f * s_aggU[d]) / den;
        }
    }
    __syncthreads();

    // R2
    {
        float v = 0.f;
        if (warp == 0)      v = s_kg[lane] * s_kg[lane]   + s_kg[lane + 32] * s_kg[lane + 32];
        else if (warp == 1) v = s_self[lane] * s_kg[lane] + s_self[lane + 32] * s_kg[lane + 32];
        else if (warp == 2) v = s_ua[lane] * s_ua[lane]   + s_ua[lane + 32] * s_ua[lane + 32];
        v = wred32(v);
        if (lane == 0) {
            if (warp == 0) sc[N2KG] = v; else if (warp == 1) sc[DSKG] = v;
            else if (warp == 2) sc[N2UA] = v;
        }
    }
    __syncthreads();

    // o1 = mobius_add(self, kg)
    if (tid < 64) {
        float x2 = sc[X2SELF], y2 = sc[N2KG], xy = sc[DSKG];
        float den = fmaxf(1.f + 2.f * xy + x2 * y2, 1e-15f);
        s_o1[tid] = ((1.f + 2.f * xy + y2) * s_self[tid] + (1.f - x2) * s_kg[tid]) / den;
    }
    __syncthreads();

    // R3
    {
        float v = 0.f;
        if (warp == 0)      v = s_o1[lane] * s_o1[lane] + s_o1[lane + 32] * s_o1[lane + 32];
        else if (warp == 1) v = s_o1[lane] * s_ua[lane] + s_o1[lane + 32] * s_ua[lane + 32];
        v = wred32(v);
        if (lane == 0) { if (warp == 0) sc[N2O1] = v; else if (warp == 1) sc[DO1UA] = v; }
    }
    __syncthreads();

    // o2 = mobius_add(o1, ua)
    if (tid < 64) {
        float x2 = sc[N2O1], y2 = sc[N2UA], xy = sc[DO1UA];
        float den = fmaxf(1.f + 2.f * xy + x2 * y2, 1e-15f);
        s_o2[tid] = ((1.f + 2.f * xy + y2) * s_o1[tid] + (1.f - x2) * s_ua[tid]) / den;
    }
    __syncthreads();

    // mx = lin_W @ o2
#pragma unroll
    for (int r = warp; r < 64; r += 8) {
        float v = g_linW[r * 64 + lane] * s_o2[lane]
                + g_linW[r * 64 + lane + 32] * s_o2[lane + 32];
        v = wred32(v);
        if (lane == 0) s_mx[r] = v;
    }
    __syncthreads();

    // R5
    {
        float v = 0.f;
        if (warp == 0)      { float a = s_mx[lane],    c = s_mx[lane + 32];    v = a * a + c * c; }
        else if (warp == 1) { float a = g_linb[lane],  c = g_linb[lane + 32];  v = a * a + c * c; }
        else if (warp == 2) { float a = s_o2[lane],    c = s_o2[lane + 32];    v = a * a + c * c; }
        v = wred32(v);
        if (lane == 0) {
            if (warp == 0) sc[MXN2] = v; else if (warp == 1) sc[NB2] = v;
            else if (warp == 2) sc[XN2] = v;
        }
    }
    __syncthreads();

    // res = mobius_matvec scale; hb = expmap0(lin_b)
    if (tid < 64) {
        float xn  = fmaxf(sqrtf(sc[XN2]),  1e-15f);
        float mxn = fmaxf(sqrtf(sc[MXN2]), 1e-15f);
        float f = tanhf(mxn / xn * artanh_(xn)) / mxn;
        s_res[tid] = f * s_mx[tid];
    } else if (tid < 128) {
        int d = tid - 64;
        float nb = fmaxf(sqrtf(sc[NB2]), 1e-15f);
        float f = tanhf(nb) / nb;
        s_hb[d] = f * g_linb[d];
    }
    __syncthreads();

    // R6
    {
        float v = 0.f;
        if (warp == 0)      v = s_res[lane] * s_res[lane] + s_res[lane + 32] * s_res[lane + 32];
        else if (warp == 1) v = s_hb[lane]  * s_hb[lane]  + s_hb[lane + 32]  * s_hb[lane + 32];
        else if (warp == 2) v = s_res[lane] * s_hb[lane]  + s_res[lane + 32] * s_hb[lane + 32];
        v = wred32(v);
        if (lane == 0) {
            if (warp == 0) sc[NRES2] = v; else if (warp == 1) sc[NHB2] = v;
            else if (warp == 2) sc[DRH] = v;
        }
    }
    __syncthreads();

    // o3 = mobius_add(proj(res), proj(hb))
    if (tid < 64) {
        float nr = fmaxf(sqrtf(sc[NRES2]), 1e-15f);
        float pr = (nr > MAXN) ? MAXN / nr : 1.f;
        float nh = fmaxf(sqrtf(sc[NHB2]), 1e-15f);
        float ph = (nh > MAXN) ? MAXN / nh : 1.f;
        float x2 = pr * pr * sc[NRES2];
        float y2 = ph * ph * sc[NHB2];
        float xy = pr * ph * sc[DRH];
        float den = fmaxf(1.f + 2.f * xy + x2 * y2, 1e-15f);
        s_o3[tid] = ((1.f + 2.f * xy + y2) * pr * s_res[tid] + (1.f - x2) * ph * s_hb[tid]) / den;
    }
    __syncthreads();

    // R7
    {
        float v = 0.f;
        if (warp == 0) v = s_o3[lane] * s_o3[lane] + s_o3[lane + 32] * s_o3[lane + 32];
        v = wred32(v);
        if (lane == 0 && warp == 0) sc[N2O3] = v;
    }
    __syncthreads();

    // t = tanh(logmap0(proj(o3)))
    if (tid < 64) {
        float n3 = fmaxf(sqrtf(sc[N2O3]), 1e-15f);
        float p3 = (n3 > MAXN) ? MAXN / n3 : 1.f;
        float np = fmaxf(p3 * n3, 1e-15f);
        float fL = artanh_(np) / np;
        s_t[tid] = tanhf(fL * p3 * s_o3[tid]);
    }
    __syncthreads();

    // R8
    {
        float v = 0.f;
        if (warp == 0) v = s_t[lane] * s_t[lane] + s_t[lane + 32] * s_t[lane + 32];
        v = wred32(v);
        if (lane == 0 && warp == 0) sc[N2T] = v;
    }
    __syncthreads();

    // out = expmap0(t)
    if (tid < 64) {
        float nt = fmaxf(sqrtf(sc[N2T]), 1e-15f);
        float f = tanhf(nt) / nt;
        g_out[b * 64 + tid] = f * s_t[tid];
    }
}

extern "C" void kernel_launch(void* const* d_in, const int* in_sizes, int n_in,
                              void* d_out, int out_size) {
    // inputs (metadata order): self_vectors, ngh_user_vectors, ngh_entity_vectors,
    //                          item_embeddings, Wr, W_ui, lin_W, lin_b
    int B = in_sizes[0] / 64;
    kgagg_kernel<<<B, 256>>>(
        (const float*)d_in[0],  // self_vectors
        (const float*)d_in[1],  // ngh_user_vectors
        (const float*)d_in[2],  // ngh_entity_vectors
        (const float*)d_in[3],  // item_embeddings
        (const float*)d_in[4],  // Wr
        (const float*)d_in[5],  // W_ui
        (const float*)d_in[6],  // lin_W
        (const float*)d_in[7],  // lin_b
        (float*)d_out);
}